// round 1
// baseline (speedup 1.0000x reference)
#include <cuda_runtime.h>
#include <cuda_bf16.h>
#include <cstdint>

// Problem constants
#define BB 2
#define HH 16
#define TT 8192
#define DD 64
#define MM 8
#define PP 32              // DD/2 rotation pairs
#define NVEC (BB*HH*TT)    // 262144 vectors per tensor

// Scratch (allocation-free rule: __device__ globals)
__device__ float g_U[HH*MM*DD];       // normalized Householder vectors
__device__ float g_cos[TT*PP];        // RoPE cos table
__device__ float g_sin[TT*PP];        // RoPE sin table

// ---------------------------------------------------------------------------
// Prep 1: U = V / sqrt(sum(V^2) + EPS^2), 128 rows of 64
// ---------------------------------------------------------------------------
__global__ void prep_u_kernel(const float* __restrict__ V) {
    int r = threadIdx.x;              // 0..127 == (h*MM + m)
    if (r >= HH*MM) return;
    const float* v = V + r * DD;
    float ss = 0.f;
    #pragma unroll
    for (int i = 0; i < DD; i++) ss += v[i] * v[i];
    float inv = 1.0f / sqrtf(ss + 1e-16f);   // EPS = 1e-8, EPS^2 = 1e-16
    #pragma unroll
    for (int i = 0; i < DD; i++) g_U[r * DD + i] = v[i] * inv;
}

// ---------------------------------------------------------------------------
// Prep 2: cos/sin table. Angle computed in f32 (matches reference rounding),
// then range-reduced in double so sinf/cosf see |r| <= pi (accurate even
// under fast-math for pos up to 8191).
// ---------------------------------------------------------------------------
__global__ void prep_tab_kernel(const float* __restrict__ pos,
                                const float* __restrict__ freq) {
    int i = blockIdx.x * blockDim.x + threadIdx.x;
    if (i >= TT * PP) return;
    int t = i >> 5;
    int j = i & 31;
    float af = pos[t] * freq[j];                       // f32, like reference
    const double twopi = 6.283185307179586476925286766559;
    double a = (double)af;
    double r = a - rint(a * (1.0 / twopi)) * twopi;    // r in [-pi, pi]
    float rf = (float)r;
    g_cos[i] = cosf(rf);
    g_sin[i] = sinf(rf);
}

// ---------------------------------------------------------------------------
// Main: one thread owns one 64-float vector (q or k), applies 8 reflections
// (U broadcast from shared), then RoPE from the table, writes output.
// Block = 256 threads = 256 consecutive t of one (tensor, b, h).
// Grid = 2 * NVEC / 256 = 4096 blocks.
// ---------------------------------------------------------------------------
__global__ void __launch_bounds__(256)
hh_rope_kernel(const float* __restrict__ q,
               const float* __restrict__ k,
               float* __restrict__ out) {
    __shared__ float4 sU[MM][DD/4];   // 2 KB: this head's 8 reflection vectors

    int gb = blockIdx.x;                    // 0..4095
    int tensor = gb >> 10;                  // 1024 blocks per tensor
    int rem = gb & 1023;
    int bh  = rem >> 5;                     // b*HH + h  (32 blocks per bh)
    int h   = bh & (HH - 1);
    int t   = ((rem & 31) << 8) + threadIdx.x;   // position within T

    // Load this head's U into shared (128 float4 of 512 total floats)
    if (threadIdx.x < 128) {
        const float4* gU4 = (const float4*)(g_U + h * MM * DD);
        ((float4*)sU)[threadIdx.x] = gU4[threadIdx.x];
    }
    __syncthreads();

    const float* src = tensor ? k : q;
    float*       dst = out + (size_t)tensor * (size_t)NVEC * DD;
    size_t base = (((size_t)bh * TT) + (size_t)t) * DD;

    // Load vector: 16 x float4 = 64 floats
    float4 z[16];
    const float4* src4 = (const float4*)(src + base);
    #pragma unroll
    for (int i = 0; i < 16; i++) z[i] = src4[i];

    // 8 Householder reflections, m = 7 .. 0 (reference applies reversed)
    #pragma unroll
    for (int m = MM - 1; m >= 0; m--) {
        float a0 = 0.f, a1 = 0.f, a2 = 0.f, a3 = 0.f;
        #pragma unroll
        for (int i = 0; i < 16; i += 4) {
            float4 u0 = sU[m][i+0], u1 = sU[m][i+1], u2 = sU[m][i+2], u3 = sU[m][i+3];
            a0 = fmaf(z[i+0].x,u0.x, fmaf(z[i+0].y,u0.y, fmaf(z[i+0].z,u0.z, fmaf(z[i+0].w,u0.w, a0))));
            a1 = fmaf(z[i+1].x,u1.x, fmaf(z[i+1].y,u1.y, fmaf(z[i+1].z,u1.z, fmaf(z[i+1].w,u1.w, a1))));
            a2 = fmaf(z[i+2].x,u2.x, fmaf(z[i+2].y,u2.y, fmaf(z[i+2].z,u2.z, fmaf(z[i+2].w,u2.w, a2))));
            a3 = fmaf(z[i+3].x,u3.x, fmaf(z[i+3].y,u3.y, fmaf(z[i+3].z,u3.z, fmaf(z[i+3].w,u3.w, a3))));
        }
        float s = -2.0f * ((a0 + a1) + (a2 + a3));
        #pragma unroll
        for (int i = 0; i < 16; i++) {
            float4 u = sU[m][i];
            z[i].x = fmaf(s, u.x, z[i].x);
            z[i].y = fmaf(s, u.y, z[i].y);
            z[i].z = fmaf(s, u.z, z[i].z);
            z[i].w = fmaf(s, u.w, z[i].w);
        }
    }

    // RoPE: pairs (2p, 2p+1). float4 z[i] covers pairs 2i and 2i+1.
    const float4* ct = (const float4*)(g_cos + (size_t)t * PP);
    const float4* st = (const float4*)(g_sin + (size_t)t * PP);
    float4* dst4 = (float4*)(dst + base);
    #pragma unroll
    for (int i = 0; i < 8; i++) {
        float4 c4 = ct[i];          // cos for pairs 4i .. 4i+3
        float4 s4 = st[i];
        float4 a = z[2*i], b = z[2*i+1];
        float4 ra, rb;
        ra.x = a.x*c4.x - a.y*s4.x;  ra.y = fmaf(a.x, s4.x, a.y*c4.x);
        ra.z = a.z*c4.y - a.w*s4.y;  ra.w = fmaf(a.z, s4.y, a.w*c4.y);
        rb.x = b.x*c4.z - b.y*s4.z;  rb.y = fmaf(b.x, s4.z, b.y*c4.z);
        rb.z = b.z*c4.w - b.w*s4.w;  rb.w = fmaf(b.z, s4.w, b.w*c4.w);
        dst4[2*i]   = ra;
        dst4[2*i+1] = rb;
    }
}

// ---------------------------------------------------------------------------
extern "C" void kernel_launch(void* const* d_in, const int* in_sizes, int n_in,
                              void* d_out, int out_size) {
    const float* q    = (const float*)d_in[0];
    const float* k    = (const float*)d_in[1];
    const float* V    = (const float*)d_in[2];
    const float* pos  = (const float*)d_in[3];
    const float* freq = (const float*)d_in[4];
    float* out = (float*)d_out;

    prep_u_kernel<<<1, 128>>>(V);
    prep_tab_kernel<<<(TT * PP) / 256, 256>>>(pos, freq);
    hh_rope_kernel<<<(2 * NVEC) / 256, 256>>>(q, k, out);
}

// round 4
// speedup vs baseline: 1.9571x; 1.9571x over previous
#include <cuda_runtime.h>
#include <cuda_bf16.h>
#include <cstdint>

// Problem constants
#define BB 2
#define HH 16
#define TT 8192
#define DD 64
#define MM 8
#define PP 32                 // DD/2 rotation pairs
#define NVEC (BB*HH*TT)       // 262144 vectors per tensor
#define VPB 128               // vectors per block
#define BLOCKS_PER_TENSOR (NVEC / VPB)   // 2048

// WY representation of the composed reflections (per head):
//   H0*H1*...*H7 = I + W * Y^T,  W columns = [u7, u6, ..., u0]
__device__ float g_Wt[HH*MM*DD];   // [h][j][i]  column j stored as row
__device__ float g_Yt[HH*MM*DD];   // [h][j][i]

// ---------------------------------------------------------------------------
// Prep: normalize V -> u_m, build WY form. One warp per head.
// lane owns elements (lane, lane+32).
// ---------------------------------------------------------------------------
__global__ void prep_wy_kernel(const float* __restrict__ V) {
    int h = blockIdx.x;
    int lane = threadIdx.x;

    float u0[MM], u1[MM];
    #pragma unroll
    for (int m = 0; m < MM; m++) {
        float a = V[(h*MM + m)*DD + lane];
        float b = V[(h*MM + m)*DD + 32 + lane];
        float ss = a*a + b*b;
        #pragma unroll
        for (int o = 16; o > 0; o >>= 1) ss += __shfl_xor_sync(0xffffffffu, ss, o);
        float inv = 1.0f / sqrtf(ss + 1e-16f);   // EPS=1e-8 -> EPS^2
        u0[m] = a * inv;
        u1[m] = b * inv;
    }

    // Build Y. Column j corresponds to reflection u_{7-j} (applied order m=7 first).
    float y0[MM], y1[MM];
    y0[0] = -2.0f * u0[7];
    y1[0] = -2.0f * u1[7];
    #pragma unroll
    for (int j = 1; j < MM; j++) {
        float a = u0[7-j], b = u1[7-j];     // new u (left-multiplied)
        float acc0 = -2.0f * a;
        float acc1 = -2.0f * b;
        #pragma unroll
        for (int c = 0; c < MM; c++) {
            if (c < j) {
                // d = w_c . u  (w_c = u_{7-c})
                float d = u0[7-c]*a + u1[7-c]*b;
                #pragma unroll
                for (int o = 16; o > 0; o >>= 1) d += __shfl_xor_sync(0xffffffffu, d, o);
                float s = -2.0f * d;
                acc0 = fmaf(s, y0[c], acc0);
                acc1 = fmaf(s, y1[c], acc1);
            }
        }
        y0[j] = acc0;
        y1[j] = acc1;
    }

    #pragma unroll
    for (int j = 0; j < MM; j++) {
        g_Wt[(h*MM + j)*DD + lane]      = u0[7-j];
        g_Wt[(h*MM + j)*DD + 32 + lane] = u1[7-j];
        g_Yt[(h*MM + j)*DD + lane]      = y0[j];
        g_Yt[(h*MM + j)*DD + 32 + lane] = y1[j];
    }
}

// ---------------------------------------------------------------------------
// Range-reduction constants: 2*pi = RC1 + RC2 + RC3, RC1/RC2 short mantissas
// so n*RC1 and n*RC2 are exact for the n values in range (n <= ~1304).
// ---------------------------------------------------------------------------
#define INV2PI 0.15915494309189535f
#define RC1 6.283203125f
#define RC2 (-1.78217887878418e-5f)
#define RC3 3.9683738e-9f

// ---------------------------------------------------------------------------
// Main kernel: block = 128 threads = 128 consecutive vectors of one (tensor,b,h).
// Coalesced load -> smem (stride-17 float4 padding) -> thread-per-vector WY
// transform -> fused axpy+RoPE -> smem -> coalesced store.
// ---------------------------------------------------------------------------
__global__ void __launch_bounds__(128, 4)
hh_rope_kernel(const float* __restrict__ q,
               const float* __restrict__ k,
               const float* __restrict__ pos,
               const float* __restrict__ freq,
               float* __restrict__ out) {
    __shared__ __align__(16) float4 sStage[VPB * 17];  // 34816 B, conflict-free
    __shared__ __align__(16) float sW[MM][DD];          // 2 KB
    __shared__ __align__(16) float sY[MM][DD];          // 2 KB
    __shared__ float sFreq[PP];
    __shared__ float sPos[VPB];

    int tid = threadIdx.x;
    int bid = blockIdx.x;
    int tensor = bid >> 11;                 // 2048 blocks per tensor
    int vloc = (bid & 2047) * VPB;          // first vector index within tensor
    int h = (vloc >> 13) & (HH - 1);
    int t0 = vloc & (TT - 1);

    // Load W/Y for this head (256 float4 total -> 2 per thread)
    {
        const float4* gW4 = (const float4*)(g_Wt + h*MM*DD);
        const float4* gY4 = (const float4*)(g_Yt + h*MM*DD);
        ((float4*)sW)[tid]       = gW4[tid];
        ((float4*)sY)[tid]       = gY4[tid];
        if (tid < PP) sFreq[tid] = freq[tid];
        sPos[tid] = pos[t0 + tid];
    }

    // Coalesced load of 128 vectors into padded smem
    const float* src = tensor ? k : q;
    const float4* src4 = (const float4*)src + (size_t)vloc * (DD/4);
    #pragma unroll
    for (int i = 0; i < 16; i++) {
        int g = tid + (i << 7);
        float4 f = src4[g];
        sStage[(g >> 4) * 17 + (g & 15)] = f;
    }
    __syncthreads();

    // Gather own vector: 16 float4 = 64 floats (conflict-free: stride 17)
    float4 z[16];
    #pragma unroll
    for (int i = 0; i < 16; i++) z[i] = sStage[tid * 17 + i];

    // Stage 1: c_j = Y_j . z   (8 independent dot products, no serial chain)
    float c[MM];
    #pragma unroll
    for (int j = 0; j < MM; j++) {
        const float4* yr = (const float4*)(&sY[j][0]);
        float a0 = 0.f, a1 = 0.f, a2 = 0.f, a3 = 0.f;
        #pragma unroll
        for (int i = 0; i < 16; i += 4) {
            float4 y0 = yr[i], y1 = yr[i+1], y2 = yr[i+2], y3 = yr[i+3];
            a0 = fmaf(z[i  ].x,y0.x, fmaf(z[i  ].y,y0.y, fmaf(z[i  ].z,y0.z, fmaf(z[i  ].w,y0.w, a0))));
            a1 = fmaf(z[i+1].x,y1.x, fmaf(z[i+1].y,y1.y, fmaf(z[i+1].z,y1.z, fmaf(z[i+1].w,y1.w, a1))));
            a2 = fmaf(z[i+2].x,y2.x, fmaf(z[i+2].y,y2.y, fmaf(z[i+2].z,y2.z, fmaf(z[i+2].w,y2.w, a2))));
            a3 = fmaf(z[i+3].x,y3.x, fmaf(z[i+3].y,y3.y, fmaf(z[i+3].z,y3.z, fmaf(z[i+3].w,y3.w, a3))));
        }
        c[j] = (a0 + a1) + (a2 + a3);
    }

    // Stage 2 fused with RoPE: per float4 (= 2 rotation pairs):
    //   z4 += sum_j W_j[4i..4i+3] * c_j, then rotate pairs, store to smem row.
    float tf = sPos[tid];
    #pragma unroll
    for (int i = 0; i < 16; i++) {
        float4 acc = z[i];
        #pragma unroll
        for (int j = 0; j < MM; j++) {
            float4 w = ((const float4*)(&sW[j][0]))[i];
            float cj = c[j];
            acc.x = fmaf(cj, w.x, acc.x);
            acc.y = fmaf(cj, w.y, acc.y);
            acc.z = fmaf(cj, w.z, acc.z);
            acc.w = fmaf(cj, w.w, acc.w);
        }
        float4 o4;
        #pragma unroll
        for (int half = 0; half < 2; half++) {
            int p = 2*i + half;
            float xe = half ? acc.z : acc.x;
            float xo = half ? acc.w : acc.y;
            float a = tf * sFreq[p];                 // matches reference f32 product
            float n = rintf(a * INV2PI);
            float r = fmaf(-n, RC1, a);
            r = fmaf(-n, RC2, r);
            r = fmaf(-n, RC3, r);                    // r in [-pi, pi], ~4e-7 abs err
            float sv = __sinf(r);
            float cv = __cosf(r);
            float re = fmaf(-xo, sv, xe * cv);
            float ro = fmaf( xo, cv, xe * sv);
            if (half == 0) { o4.x = re; o4.y = ro; }
            else           { o4.z = re; o4.w = ro; }
        }
        sStage[tid * 17 + i] = o4;   // own row: no race before the sync
    }
    __syncthreads();

    // Coalesced store (output = concat(q_rot, k_rot); block order matches)
    float4* dst4 = (float4*)out + (size_t)bid * (VPB * DD / 4);
    #pragma unroll
    for (int i = 0; i < 16; i++) {
        int g = tid + (i << 7);
        dst4[g] = sStage[(g >> 4) * 17 + (g & 15)];
    }
}

// ---------------------------------------------------------------------------
extern "C" void kernel_launch(void* const* d_in, const int* in_sizes, int n_in,
                              void* d_out, int out_size) {
    const float* q    = (const float*)d_in[0];
    const float* k    = (const float*)d_in[1];
    const float* V    = (const float*)d_in[2];
    const float* pos  = (const float*)d_in[3];
    const float* freq = (const float*)d_in[4];
    float* out = (float*)d_out;

    prep_wy_kernel<<<HH, 32>>>(V);
    hh_rope_kernel<<<2 * BLOCKS_PER_TENSOR, VPB>>>(q, k, pos, freq, out);
}